// round 8
// baseline (speedup 1.0000x reference)
#include <cuda_runtime.h>

// RNN: B=4096, T=512, I=1, H=16, O=1
//   h_t = tanh(x_t*w_ih + b_ih + b_hh + W_hh h_{t-1}), h_0=0
//   out[b] = dot(h_T, w_fc) + b_fc
//
// R8: wall = 512*C where C = per-step dependency chain (~230cy, mostly
// LDS latency + MUFU + STS->LDS visibility) and issue sits at ~48% — so
// interleave TWO independent element-chains per warp. Each warp serves 4
// elements: 2 lane-parallel groups (lanes 0-15 / 16-31) x 2
// register-interleaved chains (A/B) per group. A and B chains share no
// registers -> ptxas fills A's stall bubbles with B's work. One syncwarp
// per timestep covers both chains.
//
// Kept from R5-R7: x staged in smem (LDS.128/4 steps), r-space recurrence
// r = 1/(1+2^(K*a)) with (1-2r),K folded into packed f32x2 weights,
// 4-accumulator packed tree with x-term seeded into acc0's addend.

#define RNN_B 4096
#define RNN_T 512
#define RNN_H 16
#define XROW (RNN_T + 4)   // x row pad

__device__ __forceinline__ float ex2_approx(float x) {
    float y; asm("ex2.approx.f32 %0, %1;" : "=f"(y) : "f"(x)); return y;
}
__device__ __forceinline__ float rcp_approx(float x) {
    float y; asm("rcp.approx.f32 %0, %1;" : "=f"(y) : "f"(x)); return y;
}
__device__ __forceinline__ unsigned long long mul2(unsigned long long a, unsigned long long b) {
    unsigned long long d; asm("mul.rn.f32x2 %0, %1, %2;" : "=l"(d) : "l"(a), "l"(b)); return d;
}
__device__ __forceinline__ unsigned long long fma2(unsigned long long a, unsigned long long b, unsigned long long c) {
    unsigned long long d; asm("fma.rn.f32x2 %0, %1, %2, %3;" : "=l"(d) : "l"(a), "l"(b), "l"(c)); return d;
}
__device__ __forceinline__ unsigned long long add2(unsigned long long a, unsigned long long b) {
    unsigned long long d; asm("add.rn.f32x2 %0, %1, %2;" : "=l"(d) : "l"(a), "l"(b)); return d;
}
__device__ __forceinline__ unsigned long long packf2(float lo, float hi) {
    unsigned long long d; asm("mov.b64 %0, {%1, %2};" : "=l"(d) : "f"(lo), "f"(hi)); return d;
}
__device__ __forceinline__ float2 unpackf2(unsigned long long p) {
    float lo, hi; asm("mov.b64 {%0, %1}, %2;" : "=f"(lo), "=f"(hi) : "l"(p));
    return make_float2(lo, hi);
}
__device__ __forceinline__ void lds_v2u64(unsigned saddr, unsigned long long& a, unsigned long long& b) {
    asm volatile("ld.shared.v2.u64 {%0, %1}, [%2];" : "=l"(a), "=l"(b) : "r"(saddr));
}
__device__ __forceinline__ void sts_f32(unsigned saddr, float v) {
    asm volatile("st.shared.f32 [%0], %1;" :: "r"(saddr), "f"(v));
}

__global__ __launch_bounds__(32) void rnn_scan_kernel(
    const float* __restrict__ x,      // [B, T, 1]
    const float* __restrict__ w_ih,   // [H]
    const float* __restrict__ w_hh,   // [H, H]
    const float* __restrict__ b_ih,   // [H]
    const float* __restrict__ b_hh,   // [H]
    const float* __restrict__ w_fc,   // [H]
    const float* __restrict__ b_fc,   // [1]
    float* __restrict__ out)          // [B]
{
    __shared__ __align__(16) float sx[4 * XROW];  // 4 sequences of x (~8.3KB)
    __shared__ __align__(16) float hb[64];        // 4 r-slots of 16 floats

    const int warp = blockIdx.x;      // one warp per block
    const int lane = threadIdx.x;     // 0..31
    const int grp  = lane >> 4;       // lane-parallel group (0/1)
    const int j    = lane & 15;       // hidden row owned by this lane

    const int eA = warp * 4 + grp * 2;   // chain-A element
    const int eB = eA + 1;               // chain-B element

    // ---- Preload this warp's 4 contiguous x sequences (8KB) into smem. ----
    {
        const float4* src = reinterpret_cast<const float4*>(x + (long)warp * 4 * RNN_T);
        #pragma unroll
        for (int i = 0; i < 16; i++) {
            const int idx = i * 32 + lane;        // float4 index 0..511
            const float4 v = src[idx];
            const int f   = idx * 4;
            const int row = f >> 9;               // /512
            const int col = f & 511;
            *reinterpret_cast<float4*>(&sx[row * XROW + col]) = v;
        }
    }

    const float K = 2.8853900817779268f; // 2*log2(e)

    // Packed folded weights (same row j for both chains).
    unsigned long long wp[8];
    float wsum = 0.0f;
    {
        const float4* w4 = reinterpret_cast<const float4*>(w_hh + j * RNN_H);
        #pragma unroll
        for (int q = 0; q < 4; q++) {
            float4 rw = w4[q];
            wsum += (rw.x + rw.y) + (rw.z + rw.w);
            wp[q * 2 + 0] = packf2(-2.0f * K * rw.x, -2.0f * K * rw.y);
            wp[q * 2 + 1] = packf2(-2.0f * K * rw.z, -2.0f * K * rw.w);
        }
    }
    const float wihK  = K * w_ih[j];
    const float biasK = K * (b_ih[j] + b_hh[j] + wsum);

    // Smem r slots: chain*128B + grp*64B. Group0 -> banks 0-15,
    // group1 -> banks 16-31: conflict-free broadcast loads and stores.
    const unsigned hbase = (unsigned)__cvta_generic_to_shared(hb);
    const unsigned rbA = hbase + (unsigned)grp * 64u;
    const unsigned rbB = rbA + 128u;
    const unsigned wA  = rbA + 4u * j;
    const unsigned wB  = rbB + 4u * j;

    sts_f32(wA, 0.5f);   // r0 = 0.5  (h0 = 0)
    sts_f32(wB, 0.5f);
    __syncwarp();

    const float4* sxA = reinterpret_cast<const float4*>(&sx[(grp * 2 + 0) * XROW]);
    const float4* sxB = reinterpret_cast<const float4*>(&sx[(grp * 2 + 1) * XROW]);

    float rA = 0.5f, rB = 0.5f;

    #pragma unroll 1
    for (int t4 = 0; t4 < RNN_T / 4; t4++) {
        const float4 xvA = sxA[t4];
        const float4 xvB = sxB[t4];
        const float xsA[4] = {xvA.x, xvA.y, xvA.z, xvA.w};
        const float xsB[4] = {xvB.x, xvB.y, xvB.z, xvB.w};
        #pragma unroll
        for (int s = 0; s < 4; s++) {
            // x-terms (off critical path), seeded into acc0 addends.
            const unsigned long long seedA = packf2(fmaf(xsA[s], wihK, biasK), 0.0f);
            const unsigned long long seedB = packf2(fmaf(xsB[s], wihK, biasK), 0.0f);

            // Gather both chains' r vectors (independent loads overlap).
            unsigned long long pA0, pA1, pA2, pA3, pA4, pA5, pA6, pA7;
            unsigned long long pB0, pB1, pB2, pB3, pB4, pB5, pB6, pB7;
            lds_v2u64(rbA +  0, pA0, pA1);
            lds_v2u64(rbB +  0, pB0, pB1);
            lds_v2u64(rbA + 16, pA2, pA3);
            lds_v2u64(rbB + 16, pB2, pB3);
            lds_v2u64(rbA + 32, pA4, pA5);
            lds_v2u64(rbB + 32, pB4, pB5);
            lds_v2u64(rbA + 48, pA6, pA7);
            lds_v2u64(rbB + 48, pB6, pB7);

            // Two independent 4-accumulator packed trees (interleaved).
            unsigned long long a0 = fma2(wp[0], pA0, seedA);
            unsigned long long b0 = fma2(wp[0], pB0, seedB);
            unsigned long long a1 = mul2(wp[1], pA1);
            unsigned long long b1 = mul2(wp[1], pB1);
            unsigned long long a2 = mul2(wp[2], pA2);
            unsigned long long b2 = mul2(wp[2], pB2);
            unsigned long long a3 = mul2(wp[3], pA3);
            unsigned long long b3 = mul2(wp[3], pB3);
            a0 = fma2(wp[4], pA4, a0);
            b0 = fma2(wp[4], pB4, b0);
            a1 = fma2(wp[5], pA5, a1);
            b1 = fma2(wp[5], pB5, b1);
            a2 = fma2(wp[6], pA6, a2);
            b2 = fma2(wp[6], pB6, b2);
            a3 = fma2(wp[7], pA7, a3);
            b3 = fma2(wp[7], pB7, b3);
            a0 = add2(a0, a1);
            b0 = add2(b0, b1);
            a2 = add2(a2, a3);
            b2 = add2(b2, b3);
            a0 = add2(a0, a2);
            b0 = add2(b0, b2);
            const float2 prA = unpackf2(a0);
            const float2 prB = unpackf2(b0);
            const float accA = prA.x + prA.y;
            const float accB = prB.x + prB.y;

            // r = 1/(1 + 2^acc)  (chains' MUFUs overlap each other)
            rA = rcp_approx(1.0f + ex2_approx(accA));
            rB = rcp_approx(1.0f + ex2_approx(accB));

            sts_f32(wA, rA);
            sts_f32(wB, rB);
            __syncwarp();
        }
    }

    // h = 1 - 2r; out[e] = sum_j h[j]*w_fc[j] + b_fc
    const float wfc = w_fc[j];
    float vA = fmaf(-2.0f, rA, 1.0f) * wfc;
    float vB = fmaf(-2.0f, rB, 1.0f) * wfc;
    #pragma unroll
    for (int off = 8; off; off >>= 1) {
        vA += __shfl_xor_sync(0xffffffffu, vA, off, 16);
        vB += __shfl_xor_sync(0xffffffffu, vB, off, 16);
    }
    if (j == 0) {
        const float bfc = b_fc[0];
        out[eA] = vA + bfc;
        out[eB] = vB + bfc;
    }
}

extern "C" void kernel_launch(void* const* d_in, const int* in_sizes, int n_in,
                              void* d_out, int out_size) {
    const float* x    = (const float*)d_in[0];
    const float* w_ih = (const float*)d_in[1];
    const float* w_hh = (const float*)d_in[2];
    const float* b_ih = (const float*)d_in[3];
    const float* b_hh = (const float*)d_in[4];
    const float* w_fc = (const float*)d_in[5];
    const float* b_fc = (const float*)d_in[6];
    float* out = (float*)d_out;

    // 1024 single-warp blocks; 4 batch elements per warp
    // (2 lane-parallel groups x 2 register-interleaved chains).
    rnn_scan_kernel<<<RNN_B / 4, 32>>>(x, w_ih, w_hh, b_ih, b_hh, w_fc, b_fc, out);
}

// round 9
// speedup vs baseline: 1.3236x; 1.3236x over previous
#include <cuda_runtime.h>

// RNN: B=4096, T=512, I=1, H=16, O=1
//   h_t = tanh(x_t*w_ih + b_ih + b_hh + W_hh h_{t-1}), h_0=0
//   out[b] = dot(h_T, w_fc) + b_fc
//
// Wall = 512 * C (serial per-step chain); R6 established C~230cy with the
// smem-broadcast + packed-f32x2 structure. R9 cuts the chain's activation
// section: single MUFU.TANH (tanh.approx.f32, 16cy, 1 hop) replaces the
// r-space EX2 + FADD + RCP (44cy, 3 hops). h-space direct: no K folding,
// gather h itself. Also fixes R6's bank overlap (64B group stagger).
//
// Kept: 16 lanes/element, 2 elements/warp, 2048 warps; x staged in smem;
// double-buffered h + one syncwarp per step; packed f32x2 dot with the
// x-term seeded into accumulator 0's addend.

#define RNN_B 4096
#define RNN_T 512
#define RNN_H 16
#define XROW (RNN_T + 4)   // x row pad

__device__ __forceinline__ float tanh_approx(float x) {
    float y; asm("tanh.approx.f32 %0, %1;" : "=f"(y) : "f"(x)); return y;
}
__device__ __forceinline__ unsigned long long mul2(unsigned long long a, unsigned long long b) {
    unsigned long long d; asm("mul.rn.f32x2 %0, %1, %2;" : "=l"(d) : "l"(a), "l"(b)); return d;
}
__device__ __forceinline__ unsigned long long fma2(unsigned long long a, unsigned long long b, unsigned long long c) {
    unsigned long long d; asm("fma.rn.f32x2 %0, %1, %2, %3;" : "=l"(d) : "l"(a), "l"(b), "l"(c)); return d;
}
__device__ __forceinline__ unsigned long long add2(unsigned long long a, unsigned long long b) {
    unsigned long long d; asm("add.rn.f32x2 %0, %1, %2;" : "=l"(d) : "l"(a), "l"(b)); return d;
}
__device__ __forceinline__ unsigned long long packf2(float lo, float hi) {
    unsigned long long d; asm("mov.b64 %0, {%1, %2};" : "=l"(d) : "f"(lo), "f"(hi)); return d;
}
__device__ __forceinline__ float2 unpackf2(unsigned long long p) {
    float lo, hi; asm("mov.b64 {%0, %1}, %2;" : "=f"(lo), "=f"(hi) : "l"(p));
    return make_float2(lo, hi);
}
__device__ __forceinline__ void lds_v2u64(unsigned saddr, unsigned long long& a, unsigned long long& b) {
    asm volatile("ld.shared.v2.u64 {%0, %1}, [%2];" : "=l"(a), "=l"(b) : "r"(saddr));
}
__device__ __forceinline__ void sts_f32(unsigned saddr, float v) {
    asm volatile("st.shared.f32 [%0], %1;" :: "r"(saddr), "f"(v));
}

__global__ __launch_bounds__(32) void rnn_scan_kernel(
    const float* __restrict__ x,      // [B, T, 1]
    const float* __restrict__ w_ih,   // [H]
    const float* __restrict__ w_hh,   // [H, H]
    const float* __restrict__ b_ih,   // [H]
    const float* __restrict__ b_hh,   // [H]
    const float* __restrict__ w_fc,   // [H]
    const float* __restrict__ b_fc,   // [1]
    float* __restrict__ out)          // [B]
{
    __shared__ __align__(16) float sx[2 * XROW];  // 2 sequences of x
    __shared__ __align__(16) float hb[2][32];     // double-buffered h
                                                  // (16 floats per element,
                                                  //  64B group stagger)

    const int warp = blockIdx.x;      // one warp per block
    const int lane = threadIdx.x;     // 0..31
    const int sub  = lane >> 4;       // batch element within warp (0/1)
    const int j    = lane & 15;       // hidden row owned by this lane

    const int b = warp * 2 + sub;     // < 4096

    // ---- Preload this warp's 2 contiguous x sequences (4KB) into smem. ----
    {
        const float4* src = reinterpret_cast<const float4*>(x + (long)warp * 2 * RNN_T);
        #pragma unroll
        for (int i = 0; i < 8; i++) {
            const int idx = i * 32 + lane;        // float4 index 0..255
            const float4 v = src[idx];
            const int f   = idx * 4;
            const int row = f >> 9;               // /512
            const int col = f & 511;
            *reinterpret_cast<float4*>(&sx[row * XROW + col]) = v;
        }
    }

    // Packed weights (h-space, no folding): wp[k] = (w[j][2k], w[j][2k+1]).
    unsigned long long wp[8];
    {
        const float4* w4 = reinterpret_cast<const float4*>(w_hh + j * RNN_H);
        #pragma unroll
        for (int q = 0; q < 4; q++) {
            float4 rw = w4[q];
            wp[q * 2 + 0] = packf2(rw.x, rw.y);
            wp[q * 2 + 1] = packf2(rw.z, rw.w);
        }
    }
    const float wih  = w_ih[j];
    const float bias = b_ih[j] + b_hh[j];

    // Smem h slots: buffer A = hb[0], buffer B = hb[1]; element sub at
    // +64B stagger -> group0 banks 0-15, group1 banks 16-31 (conflict-free).
    const unsigned rA = (unsigned)__cvta_generic_to_shared(&hb[0][sub * 16]);
    const unsigned rB = rA + 128u;    // hb[1][sub*16]
    const unsigned wA = rA + 4u * j;
    const unsigned wB = rB + 4u * j;

    sts_f32(wA, 0.0f);   // h0 = 0
    __syncwarp();

    const float4* sx4 = reinterpret_cast<const float4*>(&sx[sub * XROW]);

    float h = 0.0f;

    #pragma unroll 1
    for (int t4 = 0; t4 < RNN_T / 4; t4++) {
        const float4 xv = sx4[t4];    // broadcast LDS.128 within each group
        const float xs[4] = {xv.x, xv.y, xv.z, xv.w};
        #pragma unroll
        for (int s = 0; s < 4; s++) {
            // s even: read A, write B;  s odd: read B, write A.
            const unsigned rbase = (s & 1) ? rB : rA;
            const unsigned waddr = (s & 1) ? wA : wB;

            // x-term (ready early), seeded into accumulator 0's addend.
            const unsigned long long seed = packf2(fmaf(xs[s], wih, bias), 0.0f);

            // Gather 16 h values as 8 packed f32x2 pairs.
            unsigned long long p0, p1, p2, p3, p4, p5, p6, p7;
            lds_v2u64(rbase +  0, p0, p1);
            lds_v2u64(rbase + 16, p2, p3);
            lds_v2u64(rbase + 32, p4, p5);
            lds_v2u64(rbase + 48, p6, p7);

            // 4 packed accumulators, depth 2, then 2 add2 levels.
            unsigned long long a0 = fma2(wp[0], p0, seed);
            unsigned long long a1 = mul2(wp[1], p1);
            unsigned long long a2 = mul2(wp[2], p2);
            unsigned long long a3 = mul2(wp[3], p3);
            a0 = fma2(wp[4], p4, a0);
            a1 = fma2(wp[5], p5, a1);
            a2 = fma2(wp[6], p6, a2);
            a3 = fma2(wp[7], p7, a3);
            a0 = add2(a0, a1);
            a2 = add2(a2, a3);
            a0 = add2(a0, a2);
            const float2 pr = unpackf2(a0);
            const float acc = pr.x + pr.y;

            // Single-MUFU activation (replaces EX2 + FADD + RCP).
            h = tanh_approx(acc);

            sts_f32(waddr, h);
            __syncwarp();
        }
    }

    // out[b] = sum_j h[j]*w_fc[j] + b_fc
    float v = h * w_fc[j];
    #pragma unroll
    for (int off = 8; off; off >>= 1)
        v += __shfl_xor_sync(0xffffffffu, v, off, 16);
    if (j == 0)
        out[b] = v + b_fc[0];
}

extern "C" void kernel_launch(void* const* d_in, const int* in_sizes, int n_in,
                              void* d_out, int out_size) {
    const float* x    = (const float*)d_in[0];
    const float* w_ih = (const float*)d_in[1];
    const float* w_hh = (const float*)d_in[2];
    const float* b_ih = (const float*)d_in[3];
    const float* b_hh = (const float*)d_in[4];
    const float* w_fc = (const float*)d_in[5];
    const float* b_fc = (const float*)d_in[6];
    float* out = (float*)d_out;

    // 2048 single-warp blocks; 2 batch elements per warp.
    rnn_scan_kernel<<<RNN_B / 2, 32>>>(x, w_ih, w_hh, b_ih, b_hh, w_fc, b_fc, out);
}

// round 10
// speedup vs baseline: 1.3705x; 1.0354x over previous
#include <cuda_runtime.h>

// RNN: B=4096, T=512, I=1, H=16, O=1
//   h_t = tanh(x_t*w_ih + b_ih + b_hh + W_hh h_{t-1}), h_0=0
//   out[b] = dot(h_T, w_fc) + b_fc
//
// R10: wall = 512*C; R9's C=190 was dominated by the smem h round-trip
// (STS + syncwarp + LDS ~60-80cy). Eliminate it: h lives in REGISTERS,
// gathered by shuffles. Shuffle economics fixed by the mapping: 8 lanes
// per element, lane m owns contiguous rows {2m, 2m+1}, 4 elements/warp ->
// 16 width-8 SHFLs serve 4 elements (4 SHFL/element-step; ~0.85/cyc/SM,
// under the shuffle-unit cap). Chain: 16 independent SHFLs -> pack ->
// two shared-operand packed f32x2 trees -> MUFU.TANH -> repeat.
// Kept: x staged in smem; tanh.approx activation (rel_err ~1.2e-5).

#define RNN_B 4096
#define RNN_T 512
#define RNN_H 16
#define XROW (RNN_T + 4)   // x row pad: groups' reads on distinct banks

__device__ __forceinline__ float tanh_approx(float x) {
    float y; asm("tanh.approx.f32 %0, %1;" : "=f"(y) : "f"(x)); return y;
}
__device__ __forceinline__ unsigned long long mul2(unsigned long long a, unsigned long long b) {
    unsigned long long d; asm("mul.rn.f32x2 %0, %1, %2;" : "=l"(d) : "l"(a), "l"(b)); return d;
}
__device__ __forceinline__ unsigned long long fma2(unsigned long long a, unsigned long long b, unsigned long long c) {
    unsigned long long d; asm("fma.rn.f32x2 %0, %1, %2, %3;" : "=l"(d) : "l"(a), "l"(b), "l"(c)); return d;
}
__device__ __forceinline__ unsigned long long add2(unsigned long long a, unsigned long long b) {
    unsigned long long d; asm("add.rn.f32x2 %0, %1, %2;" : "=l"(d) : "l"(a), "l"(b)); return d;
}
__device__ __forceinline__ unsigned long long packf2(float lo, float hi) {
    unsigned long long d; asm("mov.b64 %0, {%1, %2};" : "=l"(d) : "f"(lo), "f"(hi)); return d;
}
__device__ __forceinline__ float2 unpackf2(unsigned long long p) {
    float lo, hi; asm("mov.b64 {%0, %1}, %2;" : "=f"(lo), "=f"(hi) : "l"(p));
    return make_float2(lo, hi);
}

__global__ __launch_bounds__(32) void rnn_scan_kernel(
    const float* __restrict__ x,      // [B, T, 1]
    const float* __restrict__ w_ih,   // [H]
    const float* __restrict__ w_hh,   // [H, H]
    const float* __restrict__ b_ih,   // [H]
    const float* __restrict__ b_hh,   // [H]
    const float* __restrict__ w_fc,   // [H]
    const float* __restrict__ b_fc,   // [1]
    float* __restrict__ out)          // [B]
{
    __shared__ __align__(16) float sx[4 * XROW];  // 4 sequences of x (~8.3KB)

    const int warp = blockIdx.x;      // one warp per block
    const int lane = threadIdx.x;     // 0..31
    const int g    = lane >> 3;       // element within warp (0..3)
    const int m    = lane & 7;        // lane within 8-lane group

    const int e  = warp * 4 + g;      // batch element, < 4096
    const int j0 = 2 * m;             // first owned row
    const int j1 = 2 * m + 1;         // second owned row

    // ---- Preload this warp's 4 contiguous x sequences (8KB) into smem. ----
    {
        const float4* src = reinterpret_cast<const float4*>(x + (long)warp * 4 * RNN_T);
        #pragma unroll
        for (int i = 0; i < 16; i++) {
            const int idx = i * 32 + lane;        // float4 index 0..511
            const float4 v = src[idx];
            const int f   = idx * 4;
            const int row = f >> 9;               // /512
            const int col = f & 511;
            *reinterpret_cast<float4*>(&sx[row * XROW + col]) = v;
        }
    }
    __syncwarp();

    // Packed weights for both owned rows: wp0/wp1[k] = (w[j][2k], w[j][2k+1])
    unsigned long long wp0[8], wp1[8];
    {
        const float4* wa = reinterpret_cast<const float4*>(w_hh + j0 * RNN_H);
        const float4* wb = reinterpret_cast<const float4*>(w_hh + j1 * RNN_H);
        #pragma unroll
        for (int q = 0; q < 4; q++) {
            float4 ra = wa[q], rb = wb[q];
            wp0[q * 2 + 0] = packf2(ra.x, ra.y);
            wp0[q * 2 + 1] = packf2(ra.z, ra.w);
            wp1[q * 2 + 0] = packf2(rb.x, rb.y);
            wp1[q * 2 + 1] = packf2(rb.z, rb.w);
        }
    }
    const float wih0  = w_ih[j0];
    const float wih1  = w_ih[j1];
    const float bias0 = b_ih[j0] + b_hh[j0];
    const float bias1 = b_ih[j1] + b_hh[j1];

    const float4* sx4 = reinterpret_cast<const float4*>(&sx[g * XROW]);

    float h0 = 0.0f, h1 = 0.0f;       // owned hidden units (registers)

    #pragma unroll 1
    for (int t4 = 0; t4 < RNN_T / 4; t4++) {
        const float4 xv = sx4[t4];    // broadcast LDS.128 within each group
        const float xs[4] = {xv.x, xv.y, xv.z, xv.w};
        #pragma unroll
        for (int s = 0; s < 4; s++) {
            // x-terms (off critical path), seeded into tree-accum 0 addends.
            const unsigned long long seed0 = packf2(fmaf(xs[s], wih0, bias0), 0.0f);
            const unsigned long long seed1 = packf2(fmaf(xs[s], wih1, bias1), 0.0f);

            // Gather all 16 h as 8 packed pairs: lane k of this group owns
            // (h_{2k}, h_{2k+1}). 16 independent width-8 shuffles.
            unsigned long long p[8];
            #pragma unroll
            for (int k = 0; k < 8; k++) {
                const float u = __shfl_sync(0xffffffffu, h0, k, 8);
                const float v = __shfl_sync(0xffffffffu, h1, k, 8);
                p[k] = packf2(u, v);
            }

            // Two packed trees sharing operands p[k]; 4 accums, depth 2.
            unsigned long long a0 = fma2(wp0[0], p[0], seed0);
            unsigned long long b0 = fma2(wp1[0], p[0], seed1);
            unsigned long long a1 = mul2(wp0[1], p[1]);
            unsigned long long b1 = mul2(wp1[1], p[1]);
            unsigned long long a2 = mul2(wp0[2], p[2]);
            unsigned long long b2 = mul2(wp1[2], p[2]);
            unsigned long long a3 = mul2(wp0[3], p[3]);
            unsigned long long b3 = mul2(wp1[3], p[3]);
            a0 = fma2(wp0[4], p[4], a0);
            b0 = fma2(wp1[4], p[4], b0);
            a1 = fma2(wp0[5], p[5], a1);
            b1 = fma2(wp1[5], p[5], b1);
            a2 = fma2(wp0[6], p[6], a2);
            b2 = fma2(wp1[6], p[6], b2);
            a3 = fma2(wp0[7], p[7], a3);
            b3 = fma2(wp1[7], p[7], b3);
            a0 = add2(a0, a1);
            b0 = add2(b0, b1);
            a2 = add2(a2, a3);
            b2 = add2(b2, b3);
            a0 = add2(a0, a2);
            b0 = add2(b0, b2);
            const float2 prA = unpackf2(a0);
            const float2 prB = unpackf2(b0);

            h0 = tanh_approx(prA.x + prA.y);
            h1 = tanh_approx(prB.x + prB.y);
        }
    }

    // out[e] = sum_j h[j]*w_fc[j] + b_fc  (reduce over the 8-lane group)
    float v = h0 * w_fc[j0] + h1 * w_fc[j1];
    #pragma unroll
    for (int off = 4; off; off >>= 1)
        v += __shfl_xor_sync(0xffffffffu, v, off, 8);
    if (m == 0)
        out[e] = v + b_fc[0];
}

extern "C" void kernel_launch(void* const* d_in, const int* in_sizes, int n_in,
                              void* d_out, int out_size) {
    const float* x    = (const float*)d_in[0];
    const float* w_ih = (const float*)d_in[1];
    const float* w_hh = (const float*)d_in[2];
    const float* b_ih = (const float*)d_in[3];
    const float* b_hh = (const float*)d_in[4];
    const float* w_fc = (const float*)d_in[5];
    const float* b_fc = (const float*)d_in[6];
    float* out = (float*)d_out;

    // 1024 single-warp blocks; 4 batch elements per warp, 8 lanes each.
    rnn_scan_kernel<<<RNN_B / 4, 32>>>(x, w_ih, w_hh, b_ih, b_hh, w_fc, b_fc, out);
}

// round 12
// speedup vs baseline: 1.3714x; 1.0006x over previous
#include <cuda_runtime.h>

// RNN: B=4096, T=512, I=1, H=16, O=1
//   h_t = tanh(x_t*w_ih + b_ih + b_hh + W_hh h_{t-1}), h_0=0
//   out[b] = dot(h_T, w_fc) + b_fc
//
// R12: revert to full-f32 (R11's fp16 datapath failed the 1e-3 gate at
// 2.1e-3). R10's C=184cy is ~100cy own-issue (50 instr, in-order) + ~84
// exposed latency, so cut instructions with zero precision cost: the lane
// state is kept as a PACKED f32x2 pair (h_j0, h_j1) in one 64-bit register
// and shuffled as unsigned long long (2x SHFL.32 into an aligned pair) —
// the received pairs feed fma2 directly, deleting all 8 per-step packf2.
// Math is bit-identical to R10 (rel_err 1.16e-5).
//
// Mapping: 8 lanes/element, lane m owns rows {2m, 2m+1}, 4 elements/warp,
// 1024 single-warp blocks; x staged in smem; tanh.approx.f32 activation.

#define RNN_B 4096
#define RNN_T 512
#define RNN_H 16
#define XROW (RNN_T + 4)   // x row pad: groups' reads on distinct banks

__device__ __forceinline__ float tanh_approx(float x) {
    float y; asm("tanh.approx.f32 %0, %1;" : "=f"(y) : "f"(x)); return y;
}
__device__ __forceinline__ unsigned long long mul2(unsigned long long a, unsigned long long b) {
    unsigned long long d; asm("mul.rn.f32x2 %0, %1, %2;" : "=l"(d) : "l"(a), "l"(b)); return d;
}
__device__ __forceinline__ unsigned long long fma2(unsigned long long a, unsigned long long b, unsigned long long c) {
    unsigned long long d; asm("fma.rn.f32x2 %0, %1, %2, %3;" : "=l"(d) : "l"(a), "l"(b), "l"(c)); return d;
}
__device__ __forceinline__ unsigned long long add2(unsigned long long a, unsigned long long b) {
    unsigned long long d; asm("add.rn.f32x2 %0, %1, %2;" : "=l"(d) : "l"(a), "l"(b)); return d;
}
__device__ __forceinline__ unsigned long long packf2(float lo, float hi) {
    unsigned long long d; asm("mov.b64 %0, {%1, %2};" : "=l"(d) : "f"(lo), "f"(hi)); return d;
}
__device__ __forceinline__ float2 unpackf2(unsigned long long p) {
    float lo, hi; asm("mov.b64 {%0, %1}, %2;" : "=f"(lo), "=f"(hi) : "l"(p));
    return make_float2(lo, hi);
}

__global__ __launch_bounds__(32) void rnn_scan_kernel(
    const float* __restrict__ x,      // [B, T, 1]
    const float* __restrict__ w_ih,   // [H]
    const float* __restrict__ w_hh,   // [H, H]
    const float* __restrict__ b_ih,   // [H]
    const float* __restrict__ b_hh,   // [H]
    const float* __restrict__ w_fc,   // [H]
    const float* __restrict__ b_fc,   // [1]
    float* __restrict__ out)          // [B]
{
    __shared__ __align__(16) float sx[4 * XROW];  // 4 sequences of x (~8.3KB)

    const int warp = blockIdx.x;      // one warp per block
    const int lane = threadIdx.x;     // 0..31
    const int g    = lane >> 3;       // element within warp (0..3)
    const int m    = lane & 7;        // lane within 8-lane group

    const int e  = warp * 4 + g;      // batch element, < 4096
    const int j0 = 2 * m;             // first owned row
    const int j1 = 2 * m + 1;         // second owned row

    // ---- Preload this warp's 4 contiguous x sequences (8KB) into smem. ----
    {
        const float4* src = reinterpret_cast<const float4*>(x + (long)warp * 4 * RNN_T);
        #pragma unroll
        for (int i = 0; i < 16; i++) {
            const int idx = i * 32 + lane;        // float4 index 0..511
            const float4 v = src[idx];
            const int f   = idx * 4;
            const int row = f >> 9;               // /512
            const int col = f & 511;
            *reinterpret_cast<float4*>(&sx[row * XROW + col]) = v;
        }
    }
    __syncwarp();

    // Packed weights for both owned rows: wp0/wp1[k] = (w[j][2k], w[j][2k+1])
    unsigned long long wp0[8], wp1[8];
    {
        const float4* wa = reinterpret_cast<const float4*>(w_hh + j0 * RNN_H);
        const float4* wb = reinterpret_cast<const float4*>(w_hh + j1 * RNN_H);
        #pragma unroll
        for (int q = 0; q < 4; q++) {
            float4 ra = wa[q], rb = wb[q];
            wp0[q * 2 + 0] = packf2(ra.x, ra.y);
            wp0[q * 2 + 1] = packf2(ra.z, ra.w);
            wp1[q * 2 + 0] = packf2(rb.x, rb.y);
            wp1[q * 2 + 1] = packf2(rb.z, rb.w);
        }
    }
    const float wih0  = w_ih[j0];
    const float wih1  = w_ih[j1];
    const float bias0 = b_ih[j0] + b_hh[j0];
    const float bias1 = b_ih[j1] + b_hh[j1];

    const float4* sx4 = reinterpret_cast<const float4*>(&sx[g * XROW]);

    // Lane state: packed (h_j0, h_j1) f32x2 — doubles as shuffle payload.
    unsigned long long hq = packf2(0.0f, 0.0f);

    #pragma unroll 1
    for (int t4 = 0; t4 < RNN_T / 4; t4++) {
        const float4 xv = sx4[t4];    // broadcast LDS.128 within each group
        const float xs[4] = {xv.x, xv.y, xv.z, xv.w};
        #pragma unroll
        for (int s = 0; s < 4; s++) {
            // x-terms (off critical path), seeded into tree-accum 0 addends.
            const unsigned long long seed0 = packf2(fmaf(xs[s], wih0, bias0), 0.0f);
            const unsigned long long seed1 = packf2(fmaf(xs[s], wih1, bias1), 0.0f);

            // Gather all 16 h as 8 packed pairs directly: lane k of the
            // group owns (h_2k, h_2k+1) pre-packed. 64-bit shuffle lowers
            // to 2x SHFL.32 into an aligned pair — no packf2 glue.
            unsigned long long p[8];
            #pragma unroll
            for (int k = 0; k < 8; k++)
                p[k] = __shfl_sync(0xffffffffu, hq, k, 8);

            // Two packed trees sharing operands p[k]; 4 accums, depth 2.
            unsigned long long a0 = fma2(wp0[0], p[0], seed0);
            unsigned long long b0 = fma2(wp1[0], p[0], seed1);
            unsigned long long a1 = mul2(wp0[1], p[1]);
            unsigned long long b1 = mul2(wp1[1], p[1]);
            unsigned long long a2 = mul2(wp0[2], p[2]);
            unsigned long long b2 = mul2(wp1[2], p[2]);
            unsigned long long a3 = mul2(wp0[3], p[3]);
            unsigned long long b3 = mul2(wp1[3], p[3]);
            a0 = fma2(wp0[4], p[4], a0);
            b0 = fma2(wp1[4], p[4], b0);
            a1 = fma2(wp0[5], p[5], a1);
            b1 = fma2(wp1[5], p[5], b1);
            a2 = fma2(wp0[6], p[6], a2);
            b2 = fma2(wp1[6], p[6], b2);
            a3 = fma2(wp0[7], p[7], a3);
            b3 = fma2(wp1[7], p[7], b3);
            a0 = add2(a0, a1);
            b0 = add2(b0, b1);
            a2 = add2(a2, a3);
            b2 = add2(b2, b3);
            a0 = add2(a0, a2);
            b0 = add2(b0, b2);
            const float2 prA = unpackf2(a0);
            const float2 prB = unpackf2(b0);

            const float h0 = tanh_approx(prA.x + prA.y);
            const float h1 = tanh_approx(prB.x + prB.y);
            hq = packf2(h0, h1);      // single pack per step
        }
    }

    // out[e] = sum_j h[j]*w_fc[j] + b_fc  (reduce over the 8-lane group)
    const float2 hf = unpackf2(hq);
    float v = hf.x * w_fc[j0] + hf.y * w_fc[j1];
    #pragma unroll
    for (int off = 4; off; off >>= 1)
        v += __shfl_xor_sync(0xffffffffu, v, off, 8);
    if (m == 0)
        out[e] = v + b_fc[0];
}

extern "C" void kernel_launch(void* const* d_in, const int* in_sizes, int n_in,
                              void* d_out, int out_size) {
    const float* x    = (const float*)d_in[0];
    const float* w_ih = (const float*)d_in[1];
    const float* w_hh = (const float*)d_in[2];
    const float* b_ih = (const float*)d_in[3];
    const float* b_hh = (const float*)d_in[4];
    const float* w_fc = (const float*)d_in[5];
    const float* b_fc = (const float*)d_in[6];
    float* out = (float*)d_out;

    // 1024 single-warp blocks; 4 batch elements per warp, 8 lanes each.
    rnn_scan_kernel<<<RNN_B / 4, 32>>>(x, w_ih, w_hh, b_ih, b_hh, w_fc, b_fc, out);
}